// round 2
// baseline (speedup 1.0000x reference)
#include <cuda_runtime.h>

#define BATCH 4
#define CIN   256
#define HC    128
#define NPIX  4096

// ---------------- scratch (static __device__, no allocations) ----------------
__device__ float g_theta[BATCH * HC * NPIX];   // [b][d][n]
__device__ float g_phi  [BATCH * HC * NPIX];   // [b][d][n]
__device__ float g_g    [BATCH * NPIX * HC];   // [b][n][d]
__device__ float g_y    [BATCH * HC * NPIX];   // [b][d][n]

// ---------------- fast exp on the FMA pipe (avoids MUFU bottleneck) ----------
__device__ __forceinline__ float fexp(float x) {
    float t = x * 1.4426950408889634f;            // log2(e)
    t = fminf(fmaxf(t, -125.0f), 125.0f);
    float fi = rintf(t);
    float f  = t - fi;                            // f in [-0.5, 0.5]
    float p  = 1.3333558146428443e-3f;            // 2^f Taylor/minimax, deg 5
    p = fmaf(p, f, 9.618129107628477e-3f);
    p = fmaf(p, f, 5.550410866482158e-2f);
    p = fmaf(p, f, 2.402265069591007e-1f);
    p = fmaf(p, f, 6.931471805599453e-1f);
    p = fmaf(p, f, 1.0f);
    int ei = (int)fi;
    return __int_as_float(__float_as_int(p) + (ei << 23));
}

// ---------------- projection: out[o][n] = sum_c w[o][c] x[c][n] + b[o] ------
// which: 0 -> theta [b][o][n], 1 -> phi [b][o][n], 2 -> g transposed [b][n][o]
__global__ __launch_bounds__(256) void proj_kernel(
    const float* __restrict__ x, const float* __restrict__ w,
    const float* __restrict__ bias, int which)
{
    __shared__ float wT[16][132];   // [cc][o]
    __shared__ float xs[16][128];   // [cc][n]
    const int tid  = threadIdx.x;
    const int ty   = tid >> 4, tx = tid & 15;
    const int wp   = tid >> 5, lane = tid & 31;
    const int n0   = blockIdx.x * 128;
    const int b    = blockIdx.y;
    const float* xb = x + (size_t)b * CIN * NPIX;

    float acc[8][8];
#pragma unroll
    for (int i = 0; i < 8; i++)
#pragma unroll
        for (int j = 0; j < 8; j++) acc[i][j] = 0.0f;

    for (int kc = 0; kc < CIN; kc += 16) {
        __syncthreads();
#pragma unroll
        for (int s = 0; s < 8; s++) {
            int li = s * 256 + tid;
            int o = li >> 4, cc = li & 15;
            wT[cc][o] = w[o * CIN + kc + cc];
        }
#pragma unroll
        for (int r = wp; r < 16; r += 8) {
            *(float4*)&xs[r][lane * 4] =
                *(const float4*)&xb[(size_t)(kc + r) * NPIX + n0 + lane * 4];
        }
        __syncthreads();
#pragma unroll
        for (int cc = 0; cc < 16; cc++) {
            float a[8], bb[8];
            *(float4*)&a[0]  = *(float4*)&wT[cc][ty * 8];
            *(float4*)&a[4]  = *(float4*)&wT[cc][ty * 8 + 4];
            *(float4*)&bb[0] = *(float4*)&xs[cc][tx * 8];
            *(float4*)&bb[4] = *(float4*)&xs[cc][tx * 8 + 4];
#pragma unroll
            for (int i = 0; i < 8; i++)
#pragma unroll
                for (int j = 0; j < 8; j++) acc[i][j] = fmaf(a[i], bb[j], acc[i][j]);
        }
    }

    float bv[8];
    *(float4*)&bv[0] = *(const float4*)&bias[ty * 8];
    *(float4*)&bv[4] = *(const float4*)&bias[ty * 8 + 4];

    float* out = (which == 0) ? g_theta : (which == 1) ? g_phi : g_g;
    if (which < 2) {
        float* ob = out + (size_t)b * HC * NPIX;
#pragma unroll
        for (int i = 0; i < 8; i++) {
            int o = ty * 8 + i;
            float4 v0, v1;
            v0.x = acc[i][0] + bv[i]; v0.y = acc[i][1] + bv[i];
            v0.z = acc[i][2] + bv[i]; v0.w = acc[i][3] + bv[i];
            v1.x = acc[i][4] + bv[i]; v1.y = acc[i][5] + bv[i];
            v1.z = acc[i][6] + bv[i]; v1.w = acc[i][7] + bv[i];
            *(float4*)&ob[(size_t)o * NPIX + n0 + tx * 8]     = v0;
            *(float4*)&ob[(size_t)o * NPIX + n0 + tx * 8 + 4] = v1;
        }
    } else {
        float* ob = out + (size_t)b * NPIX * HC;
#pragma unroll
        for (int j = 0; j < 8; j++) {
            int n = n0 + tx * 8 + j;
            float4 v0, v1;
            v0.x = acc[0][j] + bv[0]; v0.y = acc[1][j] + bv[1];
            v0.z = acc[2][j] + bv[2]; v0.w = acc[3][j] + bv[3];
            v1.x = acc[4][j] + bv[4]; v1.y = acc[5][j] + bv[5];
            v1.z = acc[6][j] + bv[6]; v1.w = acc[7][j] + bv[7];
            *(float4*)&ob[(size_t)n * HC + ty * 8]     = v0;
            *(float4*)&ob[(size_t)n * HC + ty * 8 + 4] = v1;
        }
    }
}

// ---------------- fused attention: S = theta^T phi, softmax, O = P g --------
// One CTA handles 128 query rows (n). Streams 128-wide m tiles.
#define BSTRIDE 132
#define FLASH_SMEM ((128 * 128 + 128 * BSTRIDE + 128 * 128) * 4)

__global__ __launch_bounds__(256, 1) void flash_kernel()
{
    extern __shared__ float sm[];
    float* Tsm = sm;                       // [k][n], stride 128
    float* Bsm = sm + 128 * 128;           // [k][m] then PsT [m][n], stride 132
    float* Gsm = Bsm + 128 * BSTRIDE;      // [m][d], stride 128

    const int tid = threadIdx.x;
    const int ty = tid >> 4, tx = tid & 15;
    const int wp = tid >> 5, lane = tid & 31;
    const int n0 = blockIdx.x * 128;
    const int b  = blockIdx.y;

    const float* Tb = g_theta + (size_t)b * HC * NPIX;
    const float* Pb = g_phi   + (size_t)b * HC * NPIX;
    const float* Gb = g_g     + (size_t)b * NPIX * HC;

#pragma unroll
    for (int r = wp; r < 128; r += 8)
        *(float4*)&Tsm[r * 128 + lane * 4] =
            *(const float4*)&Tb[(size_t)r * NPIX + n0 + lane * 4];

    float oacc[8][8];
#pragma unroll
    for (int i = 0; i < 8; i++)
#pragma unroll
        for (int j = 0; j < 8; j++) oacc[i][j] = 0.0f;
    float esum[8];
#pragma unroll
    for (int j = 0; j < 8; j++) esum[j] = 0.0f;

    for (int it = 0; it < 32; it++) {
        const int m0 = it * 128;
        __syncthreads();
#pragma unroll
        for (int r = wp; r < 128; r += 8) {
            *(float4*)&Bsm[r * BSTRIDE + lane * 4] =
                *(const float4*)&Pb[(size_t)r * NPIX + m0 + lane * 4];
            *(float4*)&Gsm[r * 128 + lane * 4] =
                *(const float4*)&Gb[(size_t)(m0 + r) * HC + lane * 4];
        }
        __syncthreads();

        // S^T[m][n] = sum_k phi[k][m] * theta[k][n]; rows m = ty*8+i, cols n = tx*8+j
        float s[8][8];
#pragma unroll
        for (int i = 0; i < 8; i++)
#pragma unroll
            for (int j = 0; j < 8; j++) s[i][j] = 0.0f;
#pragma unroll 4
        for (int k = 0; k < 128; k++) {
            float a[8], bb[8];
            *(float4*)&a[0]  = *(float4*)&Bsm[k * BSTRIDE + ty * 8];
            *(float4*)&a[4]  = *(float4*)&Bsm[k * BSTRIDE + ty * 8 + 4];
            *(float4*)&bb[0] = *(float4*)&Tsm[k * 128 + tx * 8];
            *(float4*)&bb[4] = *(float4*)&Tsm[k * 128 + tx * 8 + 4];
#pragma unroll
            for (int i = 0; i < 8; i++)
#pragma unroll
                for (int j = 0; j < 8; j++) s[i][j] = fmaf(a[i], bb[j], s[i][j]);
        }

        // exp in place + partial softmax denominators (per column n)
#pragma unroll
        for (int i = 0; i < 8; i++)
#pragma unroll
            for (int j = 0; j < 8; j++) {
                s[i][j] = fexp(s[i][j]);
                esum[j] += s[i][j];
            }

        __syncthreads();   // all threads done reading Bsm as phi
#pragma unroll
        for (int i = 0; i < 8; i++) {
            float4 v0, v1;
            v0.x = s[i][0]; v0.y = s[i][1]; v0.z = s[i][2]; v0.w = s[i][3];
            v1.x = s[i][4]; v1.y = s[i][5]; v1.z = s[i][6]; v1.w = s[i][7];
            *(float4*)&Bsm[(ty * 8 + i) * BSTRIDE + tx * 8]     = v0;
            *(float4*)&Bsm[(ty * 8 + i) * BSTRIDE + tx * 8 + 4] = v1;
        }
        __syncthreads();

        // O[n][d] += sum_m PsT[m][n] * G[m][d]; rows n = ty*8+i, cols d = tx*8+j
#pragma unroll 4
        for (int m = 0; m < 128; m++) {
            float a[8], bb[8];
            *(float4*)&a[0]  = *(float4*)&Bsm[m * BSTRIDE + ty * 8];
            *(float4*)&a[4]  = *(float4*)&Bsm[m * BSTRIDE + ty * 8 + 4];
            *(float4*)&bb[0] = *(float4*)&Gsm[m * 128 + tx * 8];
            *(float4*)&bb[4] = *(float4*)&Gsm[m * 128 + tx * 8 + 4];
#pragma unroll
            for (int i = 0; i < 8; i++)
#pragma unroll
                for (int j = 0; j < 8; j++) oacc[i][j] = fmaf(a[i], bb[j], oacc[i][j]);
        }
    }

    // reduce softmax sums across ty groups (16 partials per row n)
    __syncthreads();
#pragma unroll
    for (int j = 0; j < 8; j++) Gsm[ty * 128 + tx * 8 + j] = esum[j];
    __syncthreads();
    float rinv[8];
#pragma unroll
    for (int i = 0; i < 8; i++) {
        int n = ty * 8 + i;
        float ssum = 0.0f;
#pragma unroll
        for (int t2 = 0; t2 < 16; t2++) ssum += Gsm[t2 * 128 + n];
        rinv[i] = 1.0f / ssum;
    }

    // write y as [b][d][n]
    float* Yb = g_y + (size_t)b * HC * NPIX;
#pragma unroll
    for (int j = 0; j < 8; j++) {
        int d = tx * 8 + j;
        float4 v0, v1;
        v0.x = oacc[0][j] * rinv[0]; v0.y = oacc[1][j] * rinv[1];
        v0.z = oacc[2][j] * rinv[2]; v0.w = oacc[3][j] * rinv[3];
        v1.x = oacc[4][j] * rinv[4]; v1.y = oacc[5][j] * rinv[5];
        v1.z = oacc[6][j] * rinv[6]; v1.w = oacc[7][j] * rinv[7];
        *(float4*)&Yb[(size_t)d * NPIX + n0 + ty * 8]     = v0;
        *(float4*)&Yb[(size_t)d * NPIX + n0 + ty * 8 + 4] = v1;
    }
}

// ---------------- final: z[c][n] = sum_d w_w[c][d] y[d][n] + b_w[c] + x ------
__global__ __launch_bounds__(256) void final_kernel(
    const float* __restrict__ ww, const float* __restrict__ bw,
    const float* __restrict__ x, float* __restrict__ out)
{
    __shared__ float wTs[16][132];  // [dd][c]
    __shared__ float ys[16][128];   // [dd][n]
    const int tid = threadIdx.x;
    const int ty = tid >> 4, tx = tid & 15;
    const int wp = tid >> 5, lane = tid & 31;
    const int n0 = blockIdx.x * 128;
    const int c0 = blockIdx.y * 128;
    const int b  = blockIdx.z;
    const float* Yb = g_y + (size_t)b * HC * NPIX;

    float acc[8][8];
#pragma unroll
    for (int i = 0; i < 8; i++)
#pragma unroll
        for (int j = 0; j < 8; j++) acc[i][j] = 0.0f;

    for (int kc = 0; kc < HC; kc += 16) {
        __syncthreads();
#pragma unroll
        for (int s = 0; s < 8; s++) {
            int li = s * 256 + tid;
            int c = li >> 4, dd = li & 15;
            wTs[dd][c] = ww[(size_t)(c0 + c) * HC + kc + dd];
        }
#pragma unroll
        for (int r = wp; r < 16; r += 8)
            *(float4*)&ys[r][lane * 4] =
                *(const float4*)&Yb[(size_t)(kc + r) * NPIX + n0 + lane * 4];
        __syncthreads();
#pragma unroll
        for (int dd = 0; dd < 16; dd++) {
            float a[8], bb[8];
            *(float4*)&a[0]  = *(float4*)&wTs[dd][ty * 8];
            *(float4*)&a[4]  = *(float4*)&wTs[dd][ty * 8 + 4];
            *(float4*)&bb[0] = *(float4*)&ys[dd][tx * 8];
            *(float4*)&bb[4] = *(float4*)&ys[dd][tx * 8 + 4];
#pragma unroll
            for (int i = 0; i < 8; i++)
#pragma unroll
                for (int j = 0; j < 8; j++) acc[i][j] = fmaf(a[i], bb[j], acc[i][j]);
        }
    }

    const float* xb = x + ((size_t)b * CIN + c0) * NPIX;
    float* ob = out + ((size_t)b * CIN + c0) * NPIX;
#pragma unroll
    for (int i = 0; i < 8; i++) {
        int c = ty * 8 + i;
        float bi = bw[c0 + c];
        float4 xv0 = *(const float4*)&xb[(size_t)c * NPIX + n0 + tx * 8];
        float4 xv1 = *(const float4*)&xb[(size_t)c * NPIX + n0 + tx * 8 + 4];
        float4 v0, v1;
        v0.x = acc[i][0] + bi + xv0.x; v0.y = acc[i][1] + bi + xv0.y;
        v0.z = acc[i][2] + bi + xv0.z; v0.w = acc[i][3] + bi + xv0.w;
        v1.x = acc[i][4] + bi + xv1.x; v1.y = acc[i][5] + bi + xv1.y;
        v1.z = acc[i][6] + bi + xv1.z; v1.w = acc[i][7] + bi + xv1.w;
        *(float4*)&ob[(size_t)c * NPIX + n0 + tx * 8]     = v0;
        *(float4*)&ob[(size_t)c * NPIX + n0 + tx * 8 + 4] = v1;
    }
}

// ---------------- launch --------------------------------------------------
extern "C" void kernel_launch(void* const* d_in, const int* in_sizes, int n_in,
                              void* d_out, int out_size)
{
    const float* x       = (const float*)d_in[0];
    const float* w_theta = (const float*)d_in[1];
    const float* b_theta = (const float*)d_in[2];
    const float* w_phi   = (const float*)d_in[3];
    const float* b_phi   = (const float*)d_in[4];
    const float* w_g     = (const float*)d_in[5];
    const float* b_g     = (const float*)d_in[6];
    const float* w_w     = (const float*)d_in[7];
    const float* b_w     = (const float*)d_in[8];
    float* out = (float*)d_out;

    cudaFuncSetAttribute(flash_kernel,
                         cudaFuncAttributeMaxDynamicSharedMemorySize, FLASH_SMEM);

    dim3 g1(32, BATCH);
    proj_kernel<<<g1, 256>>>(x, w_theta, b_theta, 0);
    proj_kernel<<<g1, 256>>>(x, w_phi,   b_phi,   1);
    proj_kernel<<<g1, 256>>>(x, w_g,     b_g,     2);
    flash_kernel<<<g1, 256, FLASH_SMEM>>>();
    final_kernel<<<dim3(32, 2, BATCH), 256>>>(w_w, b_w, x, out);
}

// round 7
// speedup vs baseline: 2.5540x; 2.5540x over previous
#include <cuda_runtime.h>
#include <cuda_fp16.h>
#include <cstdint>

#define BATCH 4
#define CIN   256
#define HC    128
#define NPIX  4096

// ---------------- scratch (static __device__, no allocations) ----------------
__device__ __half g_th_hi[BATCH * NPIX * HC];  // theta [b][n][d] hi
__device__ __half g_th_lo[BATCH * NPIX * HC];  // theta lo
__device__ __half g_ph_hi[BATCH * NPIX * HC];  // phi   [b][m][d] hi
__device__ __half g_ph_lo[BATCH * NPIX * HC];  // phi   lo
__device__ __half g_gh  [BATCH * HC * NPIX];   // g     [b][d][m] fp16
__device__ float  g_y   [BATCH * HC * NPIX];   // y     [b][d][n] fp32

// ---------------- helpers ----------------------------------------------------
__device__ __forceinline__ uint32_t smem_to_u32(const void* p) {
    uint32_t a;
    asm("{ .reg .u64 t; cvta.to.shared.u64 t, %1; cvt.u32.u64 %0, t; }" : "=r"(a) : "l"(p));
    return a;
}

#define LDSM4(r0, r1, r2, r3, addr) \
    asm volatile("ldmatrix.sync.aligned.m8n8.x4.shared.b16 {%0,%1,%2,%3}, [%4];" \
                 : "=r"(r0), "=r"(r1), "=r"(r2), "=r"(r3) : "r"(addr))

__device__ __forceinline__ void mma16816(float c[4], const uint32_t a[4],
                                         uint32_t b0, uint32_t b1) {
    asm volatile("mma.sync.aligned.m16n8k16.row.col.f32.f16.f16.f32 "
                 "{%0,%1,%2,%3}, {%4,%5,%6,%7}, {%8,%9}, {%0,%1,%2,%3};"
                 : "+f"(c[0]), "+f"(c[1]), "+f"(c[2]), "+f"(c[3])
                 : "r"(a[0]), "r"(a[1]), "r"(a[2]), "r"(a[3]), "r"(b0), "r"(b1));
}

__device__ __forceinline__ uint32_t pack_h2(float lo, float hi) {
    uint32_t u;
    asm("cvt.rn.f16x2.f32 %0, %1, %2;" : "=r"(u) : "f"(hi), "f"(lo));
    return u;
}

// fast exp on the FMA pipe
__device__ __forceinline__ float fexp(float x) {
    float t = x * 1.4426950408889634f;
    t = fminf(fmaxf(t, -125.0f), 125.0f);
    float fi = rintf(t);
    float f  = t - fi;
    float p  = 1.3333558146428443e-3f;
    p = fmaf(p, f, 9.618129107628477e-3f);
    p = fmaf(p, f, 5.550410866482158e-2f);
    p = fmaf(p, f, 2.402265069591007e-1f);
    p = fmaf(p, f, 6.931471805599453e-1f);
    p = fmaf(p, f, 1.0f);
    return __int_as_float(__float_as_int(p) + ((int)fi << 23));
}

// swizzled byte offset within a [rows][128 halves] tile (256B rows, 16B chunks)
#define SWZ(r, c) ((uint32_t)((r) * 256 + (((c) ^ ((r) & 7)) << 4)))

// ---------------- projection: out[o][n] = sum_c w[o][c] x[c][n] + b[o] ------
// which: 0 theta->[n][d] hi/lo, 1 phi->[m][d] hi/lo, 2 g->[d][m] fp16
__global__ __launch_bounds__(256) void proj_kernel(
    const float* __restrict__ x, const float* __restrict__ w,
    const float* __restrict__ bias, int which)
{
    __shared__ float wT[16][132];
    __shared__ float xs[16][128];
    const int tid = threadIdx.x;
    const int ty = tid >> 4, tx = tid & 15;
    const int wp = tid >> 5, lane = tid & 31;
    const int n0 = blockIdx.x * 128;
    const int b  = blockIdx.y;
    const float* xb = x + (size_t)b * CIN * NPIX;

    float acc[8][8];
#pragma unroll
    for (int i = 0; i < 8; i++)
#pragma unroll
        for (int j = 0; j < 8; j++) acc[i][j] = 0.0f;

    for (int kc = 0; kc < CIN; kc += 16) {
        __syncthreads();
#pragma unroll
        for (int s = 0; s < 8; s++) {
            int li = s * 256 + tid;
            int o = li >> 4, cc = li & 15;
            wT[cc][o] = w[o * CIN + kc + cc];
        }
#pragma unroll
        for (int r = wp; r < 16; r += 8)
            *(float4*)&xs[r][lane * 4] =
                *(const float4*)&xb[(size_t)(kc + r) * NPIX + n0 + lane * 4];
        __syncthreads();
#pragma unroll
        for (int cc = 0; cc < 16; cc++) {
            float a[8], bb[8];
            *(float4*)&a[0]  = *(float4*)&wT[cc][ty * 8];
            *(float4*)&a[4]  = *(float4*)&wT[cc][ty * 8 + 4];
            *(float4*)&bb[0] = *(float4*)&xs[cc][tx * 8];
            *(float4*)&bb[4] = *(float4*)&xs[cc][tx * 8 + 4];
#pragma unroll
            for (int i = 0; i < 8; i++)
#pragma unroll
                for (int j = 0; j < 8; j++) acc[i][j] = fmaf(a[i], bb[j], acc[i][j]);
        }
    }

    float bv[8];
    *(float4*)&bv[0] = *(const float4*)&bias[ty * 8];
    *(float4*)&bv[4] = *(const float4*)&bias[ty * 8 + 4];

    if (which < 2) {
        __half* oh = (which == 0 ? g_th_hi : g_ph_hi) + (size_t)b * NPIX * HC;
        __half* ol = (which == 0 ? g_th_lo : g_ph_lo) + (size_t)b * NPIX * HC;
#pragma unroll
        for (int j = 0; j < 8; j++) {
            int n = n0 + tx * 8 + j;
            __half hs[8], ls[8];
#pragma unroll
            for (int i = 0; i < 8; i++) {
                float v = acc[i][j] + bv[i];
                __half h = __float2half_rn(v);
                hs[i] = h;
                ls[i] = __float2half_rn(v - __half2float(h));
            }
            *(uint4*)&oh[(size_t)n * HC + ty * 8] = *(uint4*)hs;
            *(uint4*)&ol[(size_t)n * HC + ty * 8] = *(uint4*)ls;
        }
    } else {
        __half* ob = g_gh + (size_t)b * HC * NPIX;
#pragma unroll
        for (int i = 0; i < 8; i++) {
            int d = ty * 8 + i;
            __half hv[8];
#pragma unroll
            for (int q = 0; q < 8; q++) hv[q] = __float2half_rn(acc[i][q] + bv[i]);
            *(uint4*)&ob[(size_t)d * NPIX + n0 + tx * 8] = *(uint4*)hv;
        }
    }
}

// ---------------- fused mma.sync flash attention ------------------------------
#define TH_OFF 0u
#define TL_OFF 32768u
#define PHH_OFF 65536u
#define PHL_OFF 98304u
#define GG_OFF 131072u
#define PP_OFF 163840u
#define ES_OFF 196608u
#define FLASH_SMEM (196608 + 2048)

// load [128 rows][128 halves] tile (row stride rs elements) into swizzled smem
__device__ __forceinline__ void load_tile(char* dst, const __half* __restrict__ src,
                                          int rs, int tid) {
#pragma unroll
    for (int i = 0; i < 8; i++) {
        int id = tid + i * 256;
        int r = id >> 4, c = id & 15;
        uint4 v = *(const uint4*)(src + (size_t)r * rs + c * 8);
        *(uint4*)(dst + SWZ(r, c)) = v;
    }
}

__global__ __launch_bounds__(256, 1) void flash_mma_kernel()
{
    extern __shared__ char smem[];
    const uint32_t sb = smem_to_u32(smem);
    const int tid  = threadIdx.x;
    const int wid  = tid >> 5, lane = tid & 31;
    const int wy   = wid >> 1;          // n band (0..3)
    const int wx   = wid & 1;           // m half / d half (0..1)
    const int n0   = blockIdx.x * 128;
    const int b    = blockIdx.y;

    const __half* ThH = g_th_hi + ((size_t)b * NPIX + n0) * HC;
    const __half* ThL = g_th_lo + ((size_t)b * NPIX + n0) * HC;
    const __half* PhH = g_ph_hi + (size_t)b * NPIX * HC;
    const __half* PhL = g_ph_lo + (size_t)b * NPIX * HC;
    const __half* Gm  = g_gh    + (size_t)b * HC * NPIX;
    float*        Yb  = g_y     + (size_t)b * HC * NPIX;

    // resident theta tiles
    load_tile(smem + TH_OFF, ThH, HC, tid);
    load_tile(smem + TL_OFF, ThL, HC, tid);

    float oacc[2][8][4];
#pragma unroll
    for (int t = 0; t < 2; t++)
#pragma unroll
        for (int j = 0; j < 8; j++)
#pragma unroll
            for (int q = 0; q < 4; q++) oacc[t][j][q] = 0.0f;
    float esp[4]  = {0.0f, 0.0f, 0.0f, 0.0f};
    float mrun[4] = {-1e30f, -1e30f, -1e30f, -1e30f};

    // ldmatrix address components (lane-dependent)
    const int arow = (lane & 7) + ((lane >> 3) & 1) * 8;  // A row within 16
    const int acol = lane >> 4;                           // A k-chunk select
    const int brow = (lane & 7) + (lane >> 4) * 8;        // B row within 16
    const int bcol = (lane >> 3) & 1;                     // B k-chunk select

    float* HM = (float*)(smem + ES_OFF);   // [2][128] half-row maxes (reused as ES at end)

    for (int it = 0; it < 32; it++) {
        __syncthreads();
        {   // stage phi hi/lo + g tiles for this m-block
            const int m0 = it * 128;
            load_tile(smem + PHH_OFF, PhH + (size_t)m0 * HC, HC, tid);
            load_tile(smem + PHL_OFF, PhL + (size_t)m0 * HC, HC, tid);
#pragma unroll
            for (int i = 0; i < 8; i++) {
                int id = tid + i * 256;
                int r = id >> 4, c = id & 15;
                uint4 v = *(const uint4*)(Gm + (size_t)r * NPIX + m0 + c * 8);
                *(uint4*)(smem + GG_OFF + SWZ(r, c)) = v;
            }
        }
        __syncthreads();

        // ---- MMA1: S = theta^T phi with fp16 hi/lo 3-chain --------------
        float sacc[2][8][4];
#pragma unroll
        for (int t = 0; t < 2; t++)
#pragma unroll
            for (int j = 0; j < 8; j++)
#pragma unroll
                for (int q = 0; q < 4; q++) sacc[t][j][q] = 0.0f;

#pragma unroll
        for (int kk = 0; kk < 8; kk++) {
            uint32_t ah[2][4], al[2][4];
#pragma unroll
            for (int t = 0; t < 2; t++) {
                int r = wy * 32 + t * 16 + arow;
                int c = 2 * kk + acol;
                LDSM4(ah[t][0], ah[t][1], ah[t][2], ah[t][3], sb + TH_OFF + SWZ(r, c));
                LDSM4(al[t][0], al[t][1], al[t][2], al[t][3], sb + TL_OFF + SWZ(r, c));
            }
#pragma unroll
            for (int p = 0; p < 4; p++) {
                int r = wx * 64 + p * 16 + brow;
                int c = 2 * kk + bcol;
                uint32_t bh0, bh1, bh2, bh3, bl0, bl1, bl2, bl3;
                LDSM4(bh0, bh1, bh2, bh3, sb + PHH_OFF + SWZ(r, c));
                LDSM4(bl0, bl1, bl2, bl3, sb + PHL_OFF + SWZ(r, c));
#pragma unroll
                for (int t = 0; t < 2; t++) {
                    mma16816(sacc[t][2 * p],     ah[t], bh0, bh1);
                    mma16816(sacc[t][2 * p],     ah[t], bl0, bl1);
                    mma16816(sacc[t][2 * p],     al[t], bh0, bh1);
                    mma16816(sacc[t][2 * p + 1], ah[t], bh2, bh3);
                    mma16816(sacc[t][2 * p + 1], ah[t], bl2, bl3);
                    mma16816(sacc[t][2 * p + 1], al[t], bh2, bh3);
                }
            }
        }

        // ---- online softmax: tile row max, cross-warp exchange -----------
        float mt[4] = {-1e30f, -1e30f, -1e30f, -1e30f};
#pragma unroll
        for (int t = 0; t < 2; t++)
#pragma unroll
            for (int j = 0; j < 8; j++) {
                mt[t * 2 + 0] = fmaxf(mt[t * 2 + 0], fmaxf(sacc[t][j][0], sacc[t][j][1]));
                mt[t * 2 + 1] = fmaxf(mt[t * 2 + 1], fmaxf(sacc[t][j][2], sacc[t][j][3]));
            }
#pragma unroll
        for (int q = 0; q < 4; q++) {
            mt[q] = fmaxf(mt[q], __shfl_xor_sync(0xFFFFFFFFu, mt[q], 1));
            mt[q] = fmaxf(mt[q], __shfl_xor_sync(0xFFFFFFFFu, mt[q], 2));
        }
        if ((lane & 3) == 0) {
#pragma unroll
            for (int t = 0; t < 2; t++)
#pragma unroll
                for (int h = 0; h < 2; h++)
                    HM[wx * 128 + wy * 32 + t * 16 + h * 8 + (lane >> 2)] = mt[t * 2 + h];
        }
        __syncthreads();

        float Mn[4], sc[4];
#pragma unroll
        for (int t = 0; t < 2; t++)
#pragma unroll
            for (int h = 0; h < 2; h++) {
                int q = t * 2 + h;
                int row = wy * 32 + t * 16 + h * 8 + (lane >> 2);
                float tm = fmaxf(HM[row], HM[128 + row]);
                Mn[q] = fmaxf(mrun[q], tm);
                sc[q] = fexp(mrun[q] - Mn[q]);
                mrun[q] = Mn[q];
                esp[q] *= sc[q];
            }
#pragma unroll
        for (int t = 0; t < 2; t++)
#pragma unroll
            for (int j = 0; j < 8; j++) {
                oacc[t][j][0] *= sc[t * 2];     oacc[t][j][1] *= sc[t * 2];
                oacc[t][j][2] *= sc[t * 2 + 1]; oacc[t][j][3] *= sc[t * 2 + 1];
            }

        // ---- epilogue: shifted exp, esum, pack fp16, store P to smem -----
#pragma unroll
        for (int t = 0; t < 2; t++) {
            int row0 = wy * 32 + t * 16 + (lane >> 2);
#pragma unroll
            for (int j = 0; j < 8; j++) {
                float e0 = fexp(sacc[t][j][0] - Mn[t * 2]);
                float e1 = fexp(sacc[t][j][1] - Mn[t * 2]);
                float e2 = fexp(sacc[t][j][2] - Mn[t * 2 + 1]);
                float e3 = fexp(sacc[t][j][3] - Mn[t * 2 + 1]);
                uint32_t p01 = pack_h2(e0, e1);
                uint32_t p23 = pack_h2(e2, e3);
                __half2 h01 = *reinterpret_cast<__half2*>(&p01);
                __half2 h23 = *reinterpret_cast<__half2*>(&p23);
                esp[t * 2 + 0] += __low2float(h01) + __high2float(h01);
                esp[t * 2 + 1] += __low2float(h23) + __high2float(h23);
                int ch = wx * 8 + j;
                int byt = (lane & 3) * 4;
                *(uint32_t*)(smem + PP_OFF + SWZ(row0, ch) + byt)     = p01;
                *(uint32_t*)(smem + PP_OFF + SWZ(row0 + 8, ch) + byt) = p23;
            }
        }
        __syncthreads();

        // ---- MMA2: O += P * g (fp16, k = m = 128) ------------------------
#pragma unroll
        for (int kk = 0; kk < 8; kk++) {
            uint32_t ap[2][4];
#pragma unroll
            for (int t = 0; t < 2; t++) {
                int r = wy * 32 + t * 16 + arow;
                int c = 2 * kk + acol;
                LDSM4(ap[t][0], ap[t][1], ap[t][2], ap[t][3], sb + PP_OFF + SWZ(r, c));
            }
#pragma unroll
            for (int p = 0; p < 4; p++) {
                int r = wx * 64 + p * 16 + brow;
                int c = 2 * kk + bcol;
                uint32_t bg0, bg1, bg2, bg3;
                LDSM4(bg0, bg1, bg2, bg3, sb + GG_OFF + SWZ(r, c));
#pragma unroll
                for (int t = 0; t < 2; t++) {
                    mma16816(oacc[t][2 * p],     ap[t], bg0, bg1);
                    mma16816(oacc[t][2 * p + 1], ap[t], bg2, bg3);
                }
            }
        }
    }

    // ---- softmax denominators (both wx halves share final row max) ------
    float* ES = (float*)(smem + ES_OFF);
#pragma unroll
    for (int q = 0; q < 4; q++) {
        float v = esp[q];
        v += __shfl_xor_sync(0xFFFFFFFFu, v, 1);
        v += __shfl_xor_sync(0xFFFFFFFFu, v, 2);
        if ((lane & 3) == 0)
            ES[wx * 128 + wy * 32 + (q >> 1) * 16 + (q & 1) * 8 + (lane >> 2)] = v;
    }
    __syncthreads();

    // ---- normalize, stage O[n][d] in smem ------------------------------
    float* OSM = (float*)(smem + PHH_OFF);   // [128][129]
#pragma unroll
    for (int t = 0; t < 2; t++) {
        int row0 = wy * 32 + t * 16 + (lane >> 2);
        float rv0 = 1.0f / (ES[row0] + ES[128 + row0]);
        float rv1 = 1.0f / (ES[row0 + 8] + ES[128 + row0 + 8]);
#pragma unroll
        for (int j = 0; j < 8; j++) {
            int d = wx * 64 + j * 8 + (lane & 3) * 2;
            OSM[row0 * 129 + d]           = oacc[t][j][0] * rv0;
            OSM[row0 * 129 + d + 1]       = oacc[t][j][1] * rv0;
            OSM[(row0 + 8) * 129 + d]     = oacc[t][j][2] * rv1;
            OSM[(row0 + 8) * 129 + d + 1] = oacc[t][j][3] * rv1;
        }
    }
    __syncthreads();

    // ---- coalesced y write: y[b][d][n] ---------------------------------
#pragma unroll
    for (int i = 0; i < 16; i++) {
        int id = tid + i * 256;
        int d = id >> 5, nc = (id & 31) * 4;
        float4 v;
        v.x = OSM[(nc + 0) * 129 + d];
        v.y = OSM[(nc + 1) * 129 + d];
        v.z = OSM[(nc + 2) * 129 + d];
        v.w = OSM[(nc + 3) * 129 + d];
        *(float4*)&Yb[(size_t)d * NPIX + n0 + nc] = v;
    }
}

// ---------------- final: z[c][n] = sum_d w_w[c][d] y[d][n] + b_w[c] + x ------
__global__ __launch_bounds__(256) void final_kernel(
    const float* __restrict__ ww, const float* __restrict__ bw,
    const float* __restrict__ x, float* __restrict__ out)
{
    __shared__ float wTs[16][132];
    __shared__ float ys[16][128];
    const int tid = threadIdx.x;
    const int ty = tid >> 4, tx = tid & 15;
    const int wp = tid >> 5, lane = tid & 31;
    const int n0 = blockIdx.x * 128;
    const int c0 = blockIdx.y * 128;
    const int b  = blockIdx.z;
    const float* Yb = g_y + (size_t)b * HC * NPIX;

    float acc[8][8];
#pragma unroll
    for (int i = 0; i < 8; i++)
#pragma unroll
        for (int j = 0; j < 8; j++) acc[i][j] = 0.0f;

    for (int kc = 0; kc < HC; kc += 16) {
        __syncthreads();
#pragma unroll
        for (int s = 0; s < 8; s++) {
            int li = s * 256 + tid;
            int c = li >> 4, dd = li & 15;
            wTs[dd][c] = ww[(size_t)(c0 + c) * HC + kc + dd];
        }
#pragma unroll
        for (int r = wp; r < 16; r += 8)
            *(float4*)&ys[r][lane * 4] =
                *(const float4*)&Yb[(size_t)(kc + r) * NPIX + n0 + lane * 4];
        __syncthreads();
#pragma unroll
        for (int dd = 0; dd < 16; dd++) {
            float a[8], bb[8];
            *(float4*)&a[0]  = *(float4*)&wTs[dd][ty * 8];
            *(float4*)&a[4]  = *(float4*)&wTs[dd][ty * 8 + 4];
            *(float4*)&bb[0] = *(float4*)&ys[dd][tx * 8];
            *(float4*)&bb[4] = *(float4*)&ys[dd][tx * 8 + 4];
#pragma unroll
            for (int i = 0; i < 8; i++)
#pragma unroll
                for (int j = 0; j < 8; j++) acc[i][j] = fmaf(a[i], bb[j], acc[i][j]);
        }
    }

    const float* xb = x + ((size_t)b * CIN + c0) * NPIX;
    float* ob = out + ((size_t)b * CIN + c0) * NPIX;
#pragma unroll
    for (int i = 0; i < 8; i++) {
        int c = ty * 8 + i;
        float bi = bw[c0 + c];
        float4 xv0 = *(const float4*)&xb[(size_t)c * NPIX + n0 + tx * 8];
        float4 xv1 = *(const float4*)&xb[(size_t)c * NPIX + n0 + tx * 8 + 4];
        float4 v0, v1;
        v0.x = acc[i][0] + bi + xv0.x; v0.y = acc[i][1] + bi + xv0.y;
        v0.z = acc[i][2] + bi + xv0.z; v0.w = acc[i][3] + bi + xv0.w;
        v1.x = acc[i][4] + bi + xv1.x; v1.y = acc[i][5] + bi + xv1.y;
        v1.z = acc[i][6] + bi + xv1.z; v1.w = acc[i][7] + bi + xv1.w;
        *(float4*)&ob[(size_t)c * NPIX + n0 + tx * 8]     = v0;
        *(float4*)&ob[(size_t)c * NPIX + n0 + tx * 8 + 4] = v1;
    }
}

// ---------------- launch -----------------------------------------------------
extern "C" void kernel_launch(void* const* d_in, const int* in_sizes, int n_in,
                              void* d_out, int out_size)
{
    const float* x       = (const float*)d_in[0];
    const float* w_theta = (const float*)d_in[1];
    const float* b_theta = (const float*)d_in[2];
    const float* w_phi   = (const float*)d_in[3];
    const float* b_phi   = (const float*)d_in[4];
    const float* w_g     = (const float*)d_in[5];
    const float* b_g     = (const float*)d_in[6];
    const float* w_w     = (const float*)d_in[7];
    const float* b_w     = (const float*)d_in[8];
    float* out = (float*)d_out;

    cudaFuncSetAttribute(flash_mma_kernel,
                         cudaFuncAttributeMaxDynamicSharedMemorySize, FLASH_SMEM);

    dim3 g1(32, BATCH);
    proj_kernel<<<g1, 256>>>(x, w_theta, b_theta, 0);
    proj_kernel<<<g1, 256>>>(x, w_phi,   b_phi,   1);
    proj_kernel<<<g1, 256>>>(x, w_g,     b_g,     2);
    flash_mma_kernel<<<g1, 256, FLASH_SMEM>>>();
    final_kernel<<<dim3(32, 2, BATCH), 256>>>(w_w, b_w, x, out);
}

// round 8
// speedup vs baseline: 2.6585x; 1.0409x over previous
#include <cuda_runtime.h>
#include <cuda_fp16.h>
#include <cstdint>

#define BATCH 4
#define CIN   256
#define HC    128
#define NPIX  4096

// ---------------- scratch (static __device__, no allocations) ----------------
__device__ __half g_th_hi[BATCH * NPIX * HC];  // theta [b][n][d] hi
__device__ __half g_th_lo[BATCH * NPIX * HC];  // theta lo
__device__ __half g_ph_hi[BATCH * NPIX * HC];  // phi   [b][m][d] hi
__device__ __half g_ph_lo[BATCH * NPIX * HC];  // phi   lo
__device__ __half g_gh  [BATCH * HC * NPIX];   // g     [b][d][m] fp16
__device__ float  g_y   [BATCH * HC * NPIX];   // y     [b][d][n] fp32

// ---------------- helpers ----------------------------------------------------
__device__ __forceinline__ uint32_t smem_to_u32(const void* p) {
    uint32_t a;
    asm("{ .reg .u64 t; cvta.to.shared.u64 t, %1; cvt.u32.u64 %0, t; }" : "=r"(a) : "l"(p));
    return a;
}

#define LDSM4(r0, r1, r2, r3, addr) \
    asm volatile("ldmatrix.sync.aligned.m8n8.x4.shared.b16 {%0,%1,%2,%3}, [%4];" \
                 : "=r"(r0), "=r"(r1), "=r"(r2), "=r"(r3) : "r"(addr))

#define CP_ASYNC16(dst, src) \
    asm volatile("cp.async.cg.shared.global [%0], [%1], 16;" :: "r"(dst), "l"(src))
#define CP_COMMIT()  asm volatile("cp.async.commit_group;" ::: "memory")
#define CP_WAIT0()   asm volatile("cp.async.wait_group 0;" ::: "memory")

__device__ __forceinline__ void mma16816(float c[4], const uint32_t a[4],
                                         uint32_t b0, uint32_t b1) {
    asm volatile("mma.sync.aligned.m16n8k16.row.col.f32.f16.f16.f32 "
                 "{%0,%1,%2,%3}, {%4,%5,%6,%7}, {%8,%9}, {%0,%1,%2,%3};"
                 : "+f"(c[0]), "+f"(c[1]), "+f"(c[2]), "+f"(c[3])
                 : "r"(a[0]), "r"(a[1]), "r"(a[2]), "r"(a[3]), "r"(b0), "r"(b1));
}

__device__ __forceinline__ uint32_t pack_h2(float lo, float hi) {
    uint32_t u;
    asm("cvt.rn.f16x2.f32 %0, %1, %2;" : "=r"(u) : "f"(hi), "f"(lo));
    return u;
}

// fast exp on the FMA pipe
__device__ __forceinline__ float fexp(float x) {
    float t = x * 1.4426950408889634f;
    t = fminf(fmaxf(t, -125.0f), 125.0f);
    float fi = rintf(t);
    float f  = t - fi;
    float p  = 1.3333558146428443e-3f;
    p = fmaf(p, f, 9.618129107628477e-3f);
    p = fmaf(p, f, 5.550410866482158e-2f);
    p = fmaf(p, f, 2.402265069591007e-1f);
    p = fmaf(p, f, 6.931471805599453e-1f);
    p = fmaf(p, f, 1.0f);
    return __int_as_float(__float_as_int(p) + ((int)fi << 23));
}

// swizzled byte offset within a [rows][128 halves] tile (256B rows, 16B chunks)
#define SWZ(r, c) ((uint32_t)((r) * 256 + (((c) ^ ((r) & 7)) << 4)))

// ---------------- projection: out[o][n] = sum_c w[o][c] x[c][n] + b[o] ------
// which: 0 theta->[n][d] hi/lo, 1 phi->[m][d] hi/lo, 2 g->[d][m] fp16
__global__ __launch_bounds__(256) void proj_kernel(
    const float* __restrict__ x, const float* __restrict__ w,
    const float* __restrict__ bias, int which)
{
    __shared__ float wT[16][132];
    __shared__ float xs[16][128];
    const int tid = threadIdx.x;
    const int ty = tid >> 4, tx = tid & 15;
    const int wp = tid >> 5, lane = tid & 31;
    const int n0 = blockIdx.x * 128;
    const int b  = blockIdx.y;
    const float* xb = x + (size_t)b * CIN * NPIX;

    float acc[8][8];
#pragma unroll
    for (int i = 0; i < 8; i++)
#pragma unroll
        for (int j = 0; j < 8; j++) acc[i][j] = 0.0f;

    for (int kc = 0; kc < CIN; kc += 16) {
        __syncthreads();
#pragma unroll
        for (int s = 0; s < 8; s++) {
            int li = s * 256 + tid;
            int o = li >> 4, cc = li & 15;
            wT[cc][o] = w[o * CIN + kc + cc];
        }
#pragma unroll
        for (int r = wp; r < 16; r += 8)
            *(float4*)&xs[r][lane * 4] =
                *(const float4*)&xb[(size_t)(kc + r) * NPIX + n0 + lane * 4];
        __syncthreads();
#pragma unroll
        for (int cc = 0; cc < 16; cc++) {
            float a[8], bb[8];
            *(float4*)&a[0]  = *(float4*)&wT[cc][ty * 8];
            *(float4*)&a[4]  = *(float4*)&wT[cc][ty * 8 + 4];
            *(float4*)&bb[0] = *(float4*)&xs[cc][tx * 8];
            *(float4*)&bb[4] = *(float4*)&xs[cc][tx * 8 + 4];
#pragma unroll
            for (int i = 0; i < 8; i++)
#pragma unroll
                for (int j = 0; j < 8; j++) acc[i][j] = fmaf(a[i], bb[j], acc[i][j]);
        }
    }

    float bv[8];
    *(float4*)&bv[0] = *(const float4*)&bias[ty * 8];
    *(float4*)&bv[4] = *(const float4*)&bias[ty * 8 + 4];

    if (which < 2) {
        __half* oh = (which == 0 ? g_th_hi : g_ph_hi) + (size_t)b * NPIX * HC;
        __half* ol = (which == 0 ? g_th_lo : g_ph_lo) + (size_t)b * NPIX * HC;
#pragma unroll
        for (int j = 0; j < 8; j++) {
            int n = n0 + tx * 8 + j;
            __half hs[8], ls[8];
#pragma unroll
            for (int i = 0; i < 8; i++) {
                float v = acc[i][j] + bv[i];
                __half h = __float2half_rn(v);
                hs[i] = h;
                ls[i] = __float2half_rn(v - __half2float(h));
            }
            *(uint4*)&oh[(size_t)n * HC + ty * 8] = *(uint4*)hs;
            *(uint4*)&ol[(size_t)n * HC + ty * 8] = *(uint4*)ls;
        }
    } else {
        __half* ob = g_gh + (size_t)b * HC * NPIX;
#pragma unroll
        for (int i = 0; i < 8; i++) {
            int d = ty * 8 + i;
            __half hv[8];
#pragma unroll
            for (int q = 0; q < 8; q++) hv[q] = __float2half_rn(acc[i][q] + bv[i]);
            *(uint4*)&ob[(size_t)d * NPIX + n0 + tx * 8] = *(uint4*)hv;
        }
    }
}

// ---------------- fused mma.sync flash attention ------------------------------
#define TH_OFF  0u
#define TL_OFF  32768u
#define PHH_OFF 65536u
#define PHL_OFF 98304u
#define GG_OFF  131072u        // two 32KB buffers
#define PP_OFF  196608u
#define ES_OFF  229376u
#define FLASH_SMEM (229376 + 1024)

// async-stage a [128 rows][128 halves] tile (row stride rs) into swizzled smem
__device__ __forceinline__ void stage_tile(uint32_t dst, const __half* __restrict__ src,
                                           int rs, int tid) {
#pragma unroll
    for (int i = 0; i < 8; i++) {
        int id = tid + i * 256;
        int r = id >> 4, c = id & 15;
        CP_ASYNC16(dst + SWZ(r, c), src + (size_t)r * rs + c * 8);
    }
}

__global__ __launch_bounds__(256, 1) void flash_mma_kernel()
{
    extern __shared__ char smem[];
    const uint32_t sb = smem_to_u32(smem);
    const int tid  = threadIdx.x;
    const int wid  = tid >> 5, lane = tid & 31;
    const int wy   = wid >> 1;          // n band (0..3)
    const int wx   = wid & 1;           // m half / d half (0..1)
    const int n0   = blockIdx.x * 128;
    const int b    = blockIdx.y;

    const __half* ThH = g_th_hi + ((size_t)b * NPIX + n0) * HC;
    const __half* ThL = g_th_lo + ((size_t)b * NPIX + n0) * HC;
    const __half* PhH = g_ph_hi + (size_t)b * NPIX * HC;
    const __half* PhL = g_ph_lo + (size_t)b * NPIX * HC;
    const __half* Gm  = g_gh    + (size_t)b * HC * NPIX;
    float*        Yb  = g_y     + (size_t)b * HC * NPIX;

    // prologue: async-stage theta (resident), phi(0), g(0)
    stage_tile(sb + TH_OFF, ThH, HC, tid);
    stage_tile(sb + TL_OFF, ThL, HC, tid);
    stage_tile(sb + PHH_OFF, PhH, HC, tid);
    stage_tile(sb + PHL_OFF, PhL, HC, tid);
    stage_tile(sb + GG_OFF, Gm, NPIX, tid);
    CP_COMMIT();
    CP_WAIT0();
    __syncthreads();

    float oacc[2][8][4];
#pragma unroll
    for (int t = 0; t < 2; t++)
#pragma unroll
        for (int j = 0; j < 8; j++)
#pragma unroll
            for (int q = 0; q < 4; q++) oacc[t][j][q] = 0.0f;
    float esp[4]  = {0.0f, 0.0f, 0.0f, 0.0f};
    float mrun[4] = {-1e30f, -1e30f, -1e30f, -1e30f};

    // ldmatrix address components (lane-dependent)
    const int arow = (lane & 7) + ((lane >> 3) & 1) * 8;  // A row within 16
    const int acol = lane >> 4;                           // A k-chunk select
    const int brow = (lane & 7) + (lane >> 4) * 8;        // B row within 16
    const int bcol = (lane >> 3) & 1;                     // B k-chunk select

    float* HM = (float*)(smem + ES_OFF);   // [2][128] half-row maxes (reused as ES)

    for (int it = 0; it < 32; it++) {
        // ---- MMA1: S = theta^T phi with fp16 hi/lo 3-chain --------------
        float sacc[2][8][4];
#pragma unroll
        for (int t = 0; t < 2; t++)
#pragma unroll
            for (int j = 0; j < 8; j++)
#pragma unroll
                for (int q = 0; q < 4; q++) sacc[t][j][q] = 0.0f;

#pragma unroll
        for (int kk = 0; kk < 8; kk++) {
            uint32_t ah[2][4], al[2][4];
#pragma unroll
            for (int t = 0; t < 2; t++) {
                int r = wy * 32 + t * 16 + arow;
                int c = 2 * kk + acol;
                LDSM4(ah[t][0], ah[t][1], ah[t][2], ah[t][3], sb + TH_OFF + SWZ(r, c));
                LDSM4(al[t][0], al[t][1], al[t][2], al[t][3], sb + TL_OFF + SWZ(r, c));
            }
#pragma unroll
            for (int p = 0; p < 4; p++) {
                int r = wx * 64 + p * 16 + brow;
                int c = 2 * kk + bcol;
                uint32_t bh0, bh1, bh2, bh3, bl0, bl1, bl2, bl3;
                LDSM4(bh0, bh1, bh2, bh3, sb + PHH_OFF + SWZ(r, c));
                LDSM4(bl0, bl1, bl2, bl3, sb + PHL_OFF + SWZ(r, c));
#pragma unroll
                for (int t = 0; t < 2; t++) {
                    mma16816(sacc[t][2 * p],     ah[t], bh0, bh1);
                    mma16816(sacc[t][2 * p],     ah[t], bl0, bl1);
                    mma16816(sacc[t][2 * p],     al[t], bh0, bh1);
                    mma16816(sacc[t][2 * p + 1], ah[t], bh2, bh3);
                    mma16816(sacc[t][2 * p + 1], ah[t], bl2, bl3);
                    mma16816(sacc[t][2 * p + 1], al[t], bh2, bh3);
                }
            }
        }

        // ---- tile row max + cross-warp exchange --------------------------
        float mt[4] = {-1e30f, -1e30f, -1e30f, -1e30f};
#pragma unroll
        for (int t = 0; t < 2; t++)
#pragma unroll
            for (int j = 0; j < 8; j++) {
                mt[t * 2 + 0] = fmaxf(mt[t * 2 + 0], fmaxf(sacc[t][j][0], sacc[t][j][1]));
                mt[t * 2 + 1] = fmaxf(mt[t * 2 + 1], fmaxf(sacc[t][j][2], sacc[t][j][3]));
            }
#pragma unroll
        for (int q = 0; q < 4; q++) {
            mt[q] = fmaxf(mt[q], __shfl_xor_sync(0xFFFFFFFFu, mt[q], 1));
            mt[q] = fmaxf(mt[q], __shfl_xor_sync(0xFFFFFFFFu, mt[q], 2));
        }
        if ((lane & 3) == 0) {
#pragma unroll
            for (int t = 0; t < 2; t++)
#pragma unroll
                for (int h = 0; h < 2; h++)
                    HM[wx * 128 + wy * 32 + t * 16 + h * 8 + (lane >> 2)] = mt[t * 2 + h];
        }
        __syncthreads();   // HM visible; every warp done reading phi tiles

        // ---- prefetch next phi/g while we do softmax + MMA2 --------------
        if (it < 31) {
            const int m1 = (it + 1) * 128;
            stage_tile(sb + PHH_OFF, PhH + (size_t)m1 * HC, HC, tid);
            stage_tile(sb + PHL_OFF, PhL + (size_t)m1 * HC, HC, tid);
            stage_tile(sb + GG_OFF + ((it + 1) & 1) * 32768u, Gm + m1, NPIX, tid);
            CP_COMMIT();
        }

        // ---- online softmax rescale --------------------------------------
        float Mn[4], sc[4];
#pragma unroll
        for (int t = 0; t < 2; t++)
#pragma unroll
            for (int h = 0; h < 2; h++) {
                int q = t * 2 + h;
                int row = wy * 32 + t * 16 + h * 8 + (lane >> 2);
                float tm = fmaxf(HM[row], HM[128 + row]);
                Mn[q] = fmaxf(mrun[q], tm);
                sc[q] = fexp(mrun[q] - Mn[q]);
                mrun[q] = Mn[q];
                esp[q] *= sc[q];
            }
#pragma unroll
        for (int t = 0; t < 2; t++)
#pragma unroll
            for (int j = 0; j < 8; j++) {
                oacc[t][j][0] *= sc[t * 2];     oacc[t][j][1] *= sc[t * 2];
                oacc[t][j][2] *= sc[t * 2 + 1]; oacc[t][j][3] *= sc[t * 2 + 1];
            }

        // ---- shifted exp, esum, pack fp16, store P to smem ---------------
#pragma unroll
        for (int t = 0; t < 2; t++) {
            int row0 = wy * 32 + t * 16 + (lane >> 2);
#pragma unroll
            for (int j = 0; j < 8; j++) {
                float e0 = fexp(sacc[t][j][0] - Mn[t * 2]);
                float e1 = fexp(sacc[t][j][1] - Mn[t * 2]);
                float e2 = fexp(sacc[t][j][2] - Mn[t * 2 + 1]);
                float e3 = fexp(sacc[t][j][3] - Mn[t * 2 + 1]);
                uint32_t p01 = pack_h2(e0, e1);
                uint32_t p23 = pack_h2(e2, e3);
                __half2 h01 = *reinterpret_cast<__half2*>(&p01);
                __half2 h23 = *reinterpret_cast<__half2*>(&p23);
                esp[t * 2 + 0] += __low2float(h01) + __high2float(h01);
                esp[t * 2 + 1] += __low2float(h23) + __high2float(h23);
                int ch = wx * 8 + j;
                int byt = (lane & 3) * 4;
                *(uint32_t*)(smem + PP_OFF + SWZ(row0, ch) + byt)     = p01;
                *(uint32_t*)(smem + PP_OFF + SWZ(row0 + 8, ch) + byt) = p23;
            }
        }
        __syncthreads();   // P visible

        // ---- MMA2: O += P * g (reads current g buffer) -------------------
        const uint32_t gbase = sb + GG_OFF + (it & 1) * 32768u;
#pragma unroll
        for (int kk = 0; kk < 8; kk++) {
            uint32_t ap[2][4];
#pragma unroll
            for (int t = 0; t < 2; t++) {
                int r = wy * 32 + t * 16 + arow;
                int c = 2 * kk + acol;
                LDSM4(ap[t][0], ap[t][1], ap[t][2], ap[t][3], sb + PP_OFF + SWZ(r, c));
            }
#pragma unroll
            for (int p = 0; p < 4; p++) {
                int r = wx * 64 + p * 16 + brow;
                int c = 2 * kk + bcol;
                uint32_t bg0, bg1, bg2, bg3;
                LDSM4(bg0, bg1, bg2, bg3, gbase + SWZ(r, c));
#pragma unroll
                for (int t = 0; t < 2; t++) {
                    mma16816(oacc[t][2 * p],     ap[t], bg0, bg1);
                    mma16816(oacc[t][2 * p + 1], ap[t], bg2, bg3);
                }
            }
        }

        CP_WAIT0();        // next-iter tiles landed
        __syncthreads();
    }

    // ---- softmax denominators (both wx halves share final row max) ------
    float* ES = (float*)(smem + ES_OFF);
#pragma unroll
    for (int q = 0; q < 4; q++) {
        float v = esp[q];
        v += __shfl_xor_sync(0xFFFFFFFFu, v, 1);
        v += __shfl_xor_sync(0xFFFFFFFFu, v, 2);
        if ((lane & 3) == 0)
            ES[wx * 128 + wy * 32 + (q >> 1) * 16 + (q & 1) * 8 + (lane >> 2)] = v;
    }
    __syncthreads();

    // ---- normalize, stage O[n][d] in smem ------------------------------
    float* OSM = (float*)(smem + PHH_OFF);   // [128][129]
#pragma unroll
    for (int t = 0; t < 2; t++) {
        int row0 = wy * 32 + t * 16 + (lane >> 2);
        float rv0 = 1.0f / (ES[row0] + ES[128 + row0]);
        float rv1 = 1.0f / (ES[row0 + 8] + ES[128 + row0 + 8]);
#pragma unroll
        for (int j = 0; j < 8; j++) {
            int d = wx * 64 + j * 8 + (lane & 3) * 2;
            OSM[row0 * 129 + d]           = oacc[t][j][0] * rv0;
            OSM[row0 * 129 + d + 1]       = oacc[t][j][1] * rv0;
            OSM[(row0 + 8) * 129 + d]     = oacc[t][j][2] * rv1;
            OSM[(row0 + 8) * 129 + d + 1] = oacc[t][j][3] * rv1;
        }
    }
    __syncthreads();

    // ---- coalesced y write: y[b][d][n] ---------------------------------
#pragma unroll
    for (int i = 0; i < 16; i++) {
        int id = tid + i * 256;
        int d = id >> 5, nc = (id & 31) * 4;
        float4 v;
        v.x = OSM[(nc + 0) * 129 + d];
        v.y = OSM[(nc + 1) * 129 + d];
        v.z = OSM[(nc + 2) * 129 + d];
        v.w = OSM[(nc + 3) * 129 + d];
        *(float4*)&Yb[(size_t)d * NPIX + n0 + nc] = v;
    }
}

// ---------------- final: z[c][n] = sum_d w_w[c][d] y[d][n] + b_w[c] + x ------
__global__ __launch_bounds__(256) void final_kernel(
    const float* __restrict__ ww, const float* __restrict__ bw,
    const float* __restrict__ x, float* __restrict__ out)
{
    __shared__ float wTs[16][132];
    __shared__ float ys[16][128];
    const int tid = threadIdx.x;
    const int ty = tid >> 4, tx = tid & 15;
    const int wp = tid >> 5, lane = tid & 31;
    const int n0 = blockIdx.x * 128;
    const int c0 = blockIdx.y * 128;
    const int b  = blockIdx.z;
    const float* Yb = g_y + (size_t)b * HC * NPIX;

    float acc[8][8];
#pragma unroll
    for (int i = 0; i < 8; i++)
#pragma unroll
        for (int j = 0; j < 8; j++) acc[i][j] = 0.0f;

    for (int kc = 0; kc < HC; kc += 16) {
        __syncthreads();
#pragma unroll
        for (int s = 0; s < 8; s++) {
            int li = s * 256 + tid;
            int c = li >> 4, dd = li & 15;
            wTs[dd][c] = ww[(size_t)(c0 + c) * HC + kc + dd];
        }
#pragma unroll
        for (int r = wp; r < 16; r += 8)
            *(float4*)&ys[r][lane * 4] =
                *(const float4*)&Yb[(size_t)(kc + r) * NPIX + n0 + lane * 4];
        __syncthreads();
#pragma unroll
        for (int dd = 0; dd < 16; dd++) {
            float a[8], bb[8];
            *(float4*)&a[0]  = *(float4*)&wTs[dd][ty * 8];
            *(float4*)&a[4]  = *(float4*)&wTs[dd][ty * 8 + 4];
            *(float4*)&bb[0] = *(float4*)&ys[dd][tx * 8];
            *(float4*)&bb[4] = *(float4*)&ys[dd][tx * 8 + 4];
#pragma unroll
            for (int i = 0; i < 8; i++)
#pragma unroll
                for (int j = 0; j < 8; j++) acc[i][j] = fmaf(a[i], bb[j], acc[i][j]);
        }
    }

    const float* xb = x + ((size_t)b * CIN + c0) * NPIX;
    float* ob = out + ((size_t)b * CIN + c0) * NPIX;
#pragma unroll
    for (int i = 0; i < 8; i++) {
        int c = ty * 8 + i;
        float bi = bw[c0 + c];
        float4 xv0 = *(const float4*)&xb[(size_t)c * NPIX + n0 + tx * 8];
        float4 xv1 = *(const float4*)&xb[(size_t)c * NPIX + n0 + tx * 8 + 4];
        float4 v0, v1;
        v0.x = acc[i][0] + bi + xv0.x; v0.y = acc[i][1] + bi + xv0.y;
        v0.z = acc[i][2] + bi + xv0.z; v0.w = acc[i][3] + bi + xv0.w;
        v1.x = acc[i][4] + bi + xv1.x; v1.y = acc[i][5] + bi + xv1.y;
        v1.z = acc[i][6] + bi + xv1.z; v1.w = acc[i][7] + bi + xv1.w;
        *(float4*)&ob[(size_t)c * NPIX + n0 + tx * 8]     = v0;
        *(float4*)&ob[(size_t)c * NPIX + n0 + tx * 8 + 4] = v1;
    }
}

// ---------------- launch -----------------------------------------------------
extern "C" void kernel_launch(void* const* d_in, const int* in_sizes, int n_in,
                              void* d_out, int out_size)
{
    const float* x       = (const float*)d_in[0];
    const float* w_theta = (const float*)d_in[1];
    const float* b_theta = (const float*)d_in[2];
    const float* w_phi   = (const float*)d_in[3];
    const float* b_phi   = (const float*)d_in[4];
    const float* w_g     = (const float*)d_in[5];
    const float* b_g     = (const float*)d_in[6];
    const float* w_w     = (const float*)d_in[7];
    const float* b_w     = (const float*)d_in[8];
    float* out = (float*)d_out;

    cudaFuncSetAttribute(flash_mma_kernel,
                         cudaFuncAttributeMaxDynamicSharedMemorySize, FLASH_SMEM);

    dim3 g1(32, BATCH);
    proj_kernel<<<g1, 256>>>(x, w_theta, b_theta, 0);
    proj_kernel<<<g1, 256>>>(x, w_phi,   b_phi,   1);
    proj_kernel<<<g1, 256>>>(x, w_g,     b_g,     2);
    flash_mma_kernel<<<g1, 256, FLASH_SMEM>>>();
    final_kernel<<<dim3(32, 2, BATCH), 256>>>(w_w, b_w, x, out);
}